// round 9
// baseline (speedup 1.0000x reference)
#include <cuda_runtime.h>
#include <cuda_fp16.h>
#include <math.h>
#include <stdint.h>

#define EPSQ 1e-8f
#define TAU 2e-3f
#define NEGINF (-__int_as_float(0x7f800000))

// normalized codebook: fp32 (exact fixup) + fp16 (MMA), row-major [1024][256]
__device__ float g_cbs[1024 * 256];
__device__ __half g_Bh[1024 * 256];

__device__ __forceinline__ uint32_t smem_u32(const void* p) {
    uint32_t a;
    asm("{ .reg .u64 t; cvta.to.shared.u64 t, %1; cvt.u32.u64 %0, t; }" : "=r"(a) : "l"(p));
    return a;
}
__device__ __forceinline__ void cp16(uint32_t smem_dst, const void* gsrc) {
    asm volatile("cp.async.cg.shared.global [%0], [%1], 16;" :: "r"(smem_dst), "l"(gsrc));
}
__device__ __forceinline__ void cp_commit() { asm volatile("cp.async.commit_group;"); }
template <int Np>
__device__ __forceinline__ void cp_wait() { asm volatile("cp.async.wait_group %0;" :: "n"(Np)); }

__device__ __forceinline__ void ldsm4(uint32_t* r, uint32_t addr) {
    asm volatile("ldmatrix.sync.aligned.m8n8.x4.shared.b16 {%0,%1,%2,%3}, [%4];"
                 : "=r"(r[0]), "=r"(r[1]), "=r"(r[2]), "=r"(r[3]) : "r"(addr));
}
__device__ __forceinline__ void mma16816(float* d, const uint32_t* a, const uint32_t* b) {
    asm volatile(
        "mma.sync.aligned.m16n8k16.row.col.f32.f16.f16.f32 "
        "{%0,%1,%2,%3},{%4,%5,%6,%7},{%8,%9},{%0,%1,%2,%3};"
        : "+f"(d[0]), "+f"(d[1]), "+f"(d[2]), "+f"(d[3])
        : "r"(a[0]), "r"(a[1]), "r"(a[2]), "r"(a[3]), "r"(b[0]), "r"(b[1]));
}

// fast gumbel for screening: exact-logf fallback for u near 1 (MUFU inner-log
// underflow to 0 would give bogus +inf with huge margin -> silently wrong row).
__device__ __forceinline__ float gumbel_fast(float u) {
    if (u > 0.999f) return -logf(-logf(u));      // rare (~0.1%): exact chain
    return -__logf(-__logf(u));                  // abs err ~4e-6 << TAU
}

// ---- prep: normalize rows -> g_cbs (fp32) + g_Bh (fp16) ----
__global__ void prep_codebook(const float* __restrict__ cb, int K) {
    int row = blockIdx.x * 8 + (threadIdx.x >> 5);
    int lane = threadIdx.x & 31;
    if (row >= K) return;
    const float4* src = (const float4*)(cb + (size_t)row * 256);
    float4 a = src[lane * 2], b = src[lane * 2 + 1];
    float ss = a.x*a.x + a.y*a.y + a.z*a.z + a.w*a.w + b.x*b.x + b.y*b.y + b.z*b.z + b.w*b.w;
#pragma unroll
    for (int off = 16; off; off >>= 1) ss += __shfl_xor_sync(0xffffffffu, ss, off);
    float inv = 1.0f / fmaxf(sqrtf(ss), EPSQ);
    float v[8] = {a.x, a.y, a.z, a.w, b.x, b.y, b.z, b.w};
#pragma unroll
    for (int q = 0; q < 8; q++) {
        int k = lane * 8 + q;
        float x = v[q] * inv;
        g_cbs[(size_t)row * 256 + k] = x;
        g_Bh[(size_t)row * 256 + k] = __float2half_rn(x);
    }
}

// ---- main: M=128 CTA, chunk N=32 (32 chunks), warp grid 4x2, warp tile 32x16 ----
// smem: A_h 128x512B = 64KB @0; B 2 stages x 16KB @65536. 96KB -> 2 CTAs/SM.
__global__ void __launch_bounds__(256, 2)
quant_mma(const float* __restrict__ latent, const float* __restrict__ noise,
          const float* __restrict__ cb, const float* __restrict__ tptr,
          float* __restrict__ out, int K) {
    extern __shared__ char dsm[];
    __shared__ float s_scale[128];
    __shared__ float s_bv[256];
    __shared__ int s_bk2[256];
    __shared__ float s_sv[256];
    __shared__ int s_win[128];
    __shared__ int s_nfix;
    __shared__ int s_fixrows[16];
    __shared__ float s_rv[8];
    __shared__ int s_rk[8];

    const int tid = threadIdx.x, lane = tid & 31, wid = tid >> 5;
    const int wm = wid & 3, wn = wid >> 2;
    const int rowbase = blockIdx.x * 128;
    const uint32_t smA = smem_u32(dsm);
    const uint32_t smB = smA + 65536u;

    if (tid == 0) s_nfix = 0;

    // issue B chunks 0,1 (chunk = 32 rows x 512B, swizzled)
#pragma unroll
    for (int st = 0; st < 2; st++) {
#pragma unroll
        for (int i = 0; i < 4; i++) {
            int idx = tid + i * 256;
            int n = idx >> 5, c16 = idx & 31;
            uint32_t off = (uint32_t)(n * 512) + (uint32_t)((c16 * 16) ^ ((n & 7) << 4));
            cp16(smB + st * 16384u + off,
                 (const char*)g_Bh + ((size_t)(st * 32 + n) * 256 + c16 * 8) * 2);
        }
        cp_commit();
    }

    // A prologue: 2 threads per row, fp16 convert + swizzled store + row norm
    {
        float tv = *tptr;
        int r = tid >> 1, h2 = tid & 1;
        const float4* ar = (const float4*)(latent + (size_t)(rowbase + r) * 256);
        char* pA = dsm + r * 512;
        uint32_t swr = (uint32_t)((r & 7) << 4);
        float ss = 0.0f;
#pragma unroll
        for (int q = 0; q < 32; q++) {
            int d4 = h2 * 32 + q;
            float4 v = ar[d4];
            ss += v.x * v.x + v.y * v.y + v.z * v.z + v.w * v.w;
            __half h0 = __float2half_rn(v.x), h1 = __float2half_rn(v.y);
            __half h2a = __float2half_rn(v.z), h3 = __float2half_rn(v.w);
            uint2 hp;
            hp.x = (uint32_t)__half_as_ushort(h0) | ((uint32_t)__half_as_ushort(h1) << 16);
            hp.y = (uint32_t)__half_as_ushort(h2a) | ((uint32_t)__half_as_ushort(h3) << 16);
            *(uint2*)(pA + ((uint32_t)(d4 * 8) ^ swr)) = hp;
        }
        ss += __shfl_xor_sync(0xffffffffu, ss, 1);
        if (h2 == 0) s_scale[r] = 1.0f / (fmaxf(sqrtf(ss), EPSQ) * tv);
    }
    __syncthreads();

    // fragment address constants (verified in R4/R8)
    const int m8 = lane >> 3, rl = lane & 7;
    const uint32_t sw = (uint32_t)(rl << 4);
    const uint32_t aBase0 = smA + (uint32_t)((wm * 32 + 8 * (m8 & 1) + rl) * 512);
    const uint32_t aBase1 = aBase0 + 16 * 512;
    const uint32_t aKoff = (uint32_t)((m8 >> 1) * 16);
    const uint32_t bRow = (uint32_t)((wn * 16 + (m8 >> 1) * 8 + rl) * 512);
    const uint32_t bKoff = (uint32_t)((m8 & 1) * 16);

    // epilogue state: 4 owned rows
    const int eR = wm * 32 + (lane >> 2);
    const float* nrow[4];
    float sc[4], best[4], sec[4];
    int bk[4];
#pragma unroll
    for (int ri = 0; ri < 4; ri++) {
        int R = eR + (ri & 1) * 8 + (ri >> 1) * 16;
        nrow[ri] = noise + (size_t)(rowbase + R) * K;
        sc[ri] = s_scale[R];
        best[ri] = NEGINF; sec[ri] = NEGINF; bk[ri] = 0;
    }

    for (int c = 0; c < 32; c++) {
        // gumbel noise prefetch (overlaps cp wait)
        int cb0 = c * 32 + wn * 16 + (lane & 3) * 2;
        float2 u[4][2];
#pragma unroll
        for (int ri = 0; ri < 4; ri++) {
            u[ri][0] = *(const float2*)(nrow[ri] + cb0);
            u[ri][1] = *(const float2*)(nrow[ri] + cb0 + 8);
        }
        if (c < 31) cp_wait<1>(); else cp_wait<0>();
        __syncthreads();

        const uint32_t Bst = smB + (uint32_t)((c & 1) * 16384);
        float acc[2][2][4];
#pragma unroll
        for (int i = 0; i < 2; i++)
#pragma unroll
            for (int j = 0; j < 2; j++)
#pragma unroll
                for (int q = 0; q < 4; q++) acc[i][j][q] = 0.0f;

#pragma unroll
        for (int ks = 0; ks < 16; ks++) {
            uint32_t offA = ((uint32_t)(ks * 32) + aKoff) ^ sw;
            uint32_t offB = ((uint32_t)(ks * 32) + bKoff) ^ sw;
            uint32_t bh[4], a0[4], a1[4];
            ldsm4(bh, Bst + bRow + offB);
            ldsm4(a0, aBase0 + offA);
            ldsm4(a1, aBase1 + offA);
            mma16816(acc[0][0], a0, bh);
            mma16816(acc[0][1], a0, bh + 2);
            mma16816(acc[1][0], a1, bh);
            mma16816(acc[1][1], a1, bh + 2);
        }
        __syncthreads();

        // issue prefetch of c+2 immediately; epilogue overlaps the copy
        if (c + 2 < 32) {
            uint32_t stb = smB + (uint32_t)((c & 1) * 16384);
#pragma unroll
            for (int i = 0; i < 4; i++) {
                int idx = tid + i * 256;
                int n = idx >> 5, c16 = idx & 31;
                uint32_t off = (uint32_t)(n * 512) + (uint32_t)((c16 * 16) ^ ((n & 7) << 4));
                cp16(stb + off,
                     (const char*)g_Bh + ((size_t)((c + 2) * 32 + n) * 256 + c16 * 8) * 2);
            }
            cp_commit();
        }

        // epilogue: scale + fast gumbel + running top-2
#pragma unroll
        for (int mt = 0; mt < 2; mt++)
#pragma unroll
            for (int hi = 0; hi < 2; hi++) {
                int ri = mt * 2 + hi;
                float b0 = best[ri], s0 = sec[ri];
                int k0 = bk[ri];
#pragma unroll
                for (int nt = 0; nt < 2; nt++) {
                    float2 uu = u[ri][nt];
                    float g0 = gumbel_fast(uu.x);
                    float g1 = gumbel_fast(uu.y);
                    float l0 = fmaf(acc[mt][nt][hi * 2 + 0], sc[ri], g0);
                    float l1 = fmaf(acc[mt][nt][hi * 2 + 1], sc[ri], g1);
                    int kk = cb0 + nt * 8;
                    if (l0 > b0) { s0 = b0; b0 = l0; k0 = kk; } else if (l0 > s0) s0 = l0;
                    if (l1 > b0) { s0 = b0; b0 = l1; k0 = kk + 1; } else if (l1 > s0) s0 = l1;
                }
                best[ri] = b0; sec[ri] = s0; bk[ri] = k0;
            }
    }

    // quad reduce: union top-2 (strict >, ties -> smaller k)
#pragma unroll
    for (int ri = 0; ri < 4; ri++) {
        float v = best[ri], s2 = sec[ri];
        int k = bk[ri];
#pragma unroll
        for (int off = 1; off <= 2; off <<= 1) {
            float ov = __shfl_xor_sync(0xffffffffu, v, off);
            float os = __shfl_xor_sync(0xffffffffu, s2, off);
            int ok = __shfl_xor_sync(0xffffffffu, k, off);
            float nb = fmaxf(v, ov);
            float ns = fmaxf(fminf(v, ov), fmaxf(s2, os));
            k = (ov > v || (ov == v && ok < k)) ? ok : k;
            v = nb; s2 = ns;
        }
        if ((lane & 3) == 0) {
            int R = eR + (ri & 1) * 8 + (ri >> 1) * 16;
            s_bv[R * 2 + wn] = v;
            s_sv[R * 2 + wn] = s2;
            s_bk2[R * 2 + wn] = k;
        }
    }
    __syncthreads();
    if (tid < 128) {
        float v0 = s_bv[tid * 2], v1 = s_bv[tid * 2 + 1];
        float q0 = s_sv[tid * 2], q1 = s_sv[tid * 2 + 1];
        int k0 = s_bk2[tid * 2], k1 = s_bk2[tid * 2 + 1];
        float vb = fmaxf(v0, v1);
        float vs = fmaxf(fminf(v0, v1), fmaxf(q0, q1));
        s_win[tid] = (v1 > v0 || (v1 == v0 && k1 < k0)) ? k1 : k0;
        if (vb - vs < TAU) {
            int i = atomicAdd(&s_nfix, 1);
            if (i < 16) s_fixrows[i] = tid;
        }
    }
    __syncthreads();

    // exact fp32 fixup for flagged rows (expected ~0.25 per CTA)
    int nf = s_nfix < 16 ? s_nfix : 16;
    for (int f = 0; f < nf; f++) {
        int r = s_fixrows[f];
        const float4* a4 = (const float4*)(latent + (size_t)(rowbase + r) * 256);
        const float* nz = noise + (size_t)(rowbase + r) * K;
        float scr = s_scale[r];
        float bv = NEGINF;
        int bki = 0;
        for (int k = tid; k < K; k += 256) {
            const float4* b4 = (const float4*)(g_cbs + (size_t)k * 256);
            float dot = 0.0f;
#pragma unroll 8
            for (int d4 = 0; d4 < 64; d4++) {
                float4 av = a4[d4], bb = b4[d4];
                dot = fmaf(av.x, bb.x, dot);
                dot = fmaf(av.y, bb.y, dot);
                dot = fmaf(av.z, bb.z, dot);
                dot = fmaf(av.w, bb.w, dot);
            }
            float lg = fmaf(dot, scr, -logf(-logf(nz[k])));
            if (lg > bv) { bv = lg; bki = k; }
        }
#pragma unroll
        for (int off = 16; off >= 1; off >>= 1) {
            float ov = __shfl_xor_sync(0xffffffffu, bv, off);
            int ok = __shfl_xor_sync(0xffffffffu, bki, off);
            if (ov > bv || (ov == bv && ok < bki)) { bv = ov; bki = ok; }
        }
        if (lane == 0) { s_rv[wid] = bv; s_rk[wid] = bki; }
        __syncthreads();
        if (tid == 0) {
            float v = s_rv[0]; int kk = s_rk[0];
#pragma unroll
            for (int w = 1; w < 8; w++)
                if (s_rv[w] > v || (s_rv[w] == v && s_rk[w] < kk)) { v = s_rv[w]; kk = s_rk[w]; }
            s_win[r] = kk;
        }
        __syncthreads();
    }

    // gather winning codebook rows (original fp32 codebook)
    const float4* cb4 = (const float4*)cb;
    float4* o4 = (float4*)out;
#pragma unroll
    for (int t = 0; t < 32; t++) {
        int idx = tid + t * 256;
        int r = idx >> 6, d4 = idx & 63;
        o4[(size_t)(rowbase + r) * 64 + d4] = cb4[(size_t)s_win[r] * 64 + d4];
    }
}

extern "C" void kernel_launch(void* const* d_in, const int* in_sizes, int n_in,
                              void* d_out, int out_size) {
    const float* latent = (const float*)d_in[0];
    const float* noise  = (const float*)d_in[1];
    const float* cb     = (const float*)d_in[2];
    const float* tptr   = (const float*)d_in[3];

    double s0 = (double)in_sizes[0], s1 = (double)in_sizes[1], s2 = (double)in_sizes[2];
    int D = (int)llround(sqrt(s0 * s2 / s1));   // 256
    int K = in_sizes[2] / D;                    // 1024
    int N = in_sizes[0] / D;                    // 131072

    prep_codebook<<<K / 8, 256>>>(cb, K);

    int shm = 98304;  // 96 KB dynamic -> 2 CTAs/SM
    cudaFuncSetAttribute(quant_mma, cudaFuncAttributeMaxDynamicSharedMemorySize, shm);
    quant_mma<<<N / 128, 256, shm>>>(latent, noise, cb, tptr, (float*)d_out, K);
}

// round 10
// speedup vs baseline: 1.4679x; 1.4679x over previous
#include <cuda_runtime.h>
#include <cuda_fp16.h>
#include <math.h>
#include <stdint.h>

#define EPSQ 1e-8f
#define TAU 2e-3f
#define NEGINF (-__int_as_float(0x7f800000))

// normalized codebook: fp32 (exact fixup) + fp16 (MMA), row-major [1024][256]
__device__ float g_cbs[1024 * 256];
__device__ __half g_Bh[1024 * 256];

__device__ __forceinline__ uint32_t smem_u32(const void* p) {
    uint32_t a;
    asm("{ .reg .u64 t; cvta.to.shared.u64 t, %1; cvt.u32.u64 %0, t; }" : "=r"(a) : "l"(p));
    return a;
}
__device__ __forceinline__ void cp16(uint32_t smem_dst, const void* gsrc) {
    asm volatile("cp.async.cg.shared.global [%0], [%1], 16;" :: "r"(smem_dst), "l"(gsrc));
}
__device__ __forceinline__ void cp_commit() { asm volatile("cp.async.commit_group;"); }
template <int Np>
__device__ __forceinline__ void cp_wait() { asm volatile("cp.async.wait_group %0;" :: "n"(Np)); }

__device__ __forceinline__ void ldsm4(uint32_t* r, uint32_t addr) {
    asm volatile("ldmatrix.sync.aligned.m8n8.x4.shared.b16 {%0,%1,%2,%3}, [%4];"
                 : "=r"(r[0]), "=r"(r[1]), "=r"(r[2]), "=r"(r[3]) : "r"(addr));
}
__device__ __forceinline__ void mma16816(float* d, const uint32_t* a, const uint32_t* b) {
    asm volatile(
        "mma.sync.aligned.m16n8k16.row.col.f32.f16.f16.f32 "
        "{%0,%1,%2,%3},{%4,%5,%6,%7},{%8,%9},{%0,%1,%2,%3};"
        : "+f"(d[0]), "+f"(d[1]), "+f"(d[2]), "+f"(d[3])
        : "r"(a[0]), "r"(a[1]), "r"(a[2]), "r"(a[3]), "r"(b[0]), "r"(b[1]));
}

// Branchless screening gumbel. MUFU path for normal u; for u near 1 the inner
// -log(u) is replaced by an exact log1p polynomial (selp, NO branch) because
// MUFU lg2's absolute error makes -__logf(u) garbage as u->1.
// Total abs error ~1e-6 << TAU; flagged rows get the exact logf chain later.
__device__ __forceinline__ float gumbel_fast(float u) {
    float d = u - 1.0f;                                      // exact near 1
    float t_near = -d * fmaf(fmaf(0.33333334f, d, -0.5f), d, 1.0f);  // -log1p(d), rel err <1e-9
    float t_far;
    asm("lg2.approx.f32 %0, %1;" : "=f"(t_far) : "f"(u));
    t_far = t_far * (-0.6931472f);                           // -__logf(u)
    float t = (u > 0.999f) ? t_near : t_far;                 // selp, no BSSY
    float g;
    asm("lg2.approx.f32 %0, %1;" : "=f"(g) : "f"(t));
    return g * (-0.6931472f);
}

// ---- prep: normalize rows -> g_cbs (fp32) + g_Bh (fp16) ----
__global__ void prep_codebook(const float* __restrict__ cb, int K) {
    int row = blockIdx.x * 8 + (threadIdx.x >> 5);
    int lane = threadIdx.x & 31;
    if (row >= K) return;
    const float4* src = (const float4*)(cb + (size_t)row * 256);
    float4 a = src[lane * 2], b = src[lane * 2 + 1];
    float ss = a.x*a.x + a.y*a.y + a.z*a.z + a.w*a.w + b.x*b.x + b.y*b.y + b.z*b.z + b.w*b.w;
#pragma unroll
    for (int off = 16; off; off >>= 1) ss += __shfl_xor_sync(0xffffffffu, ss, off);
    float inv = 1.0f / fmaxf(sqrtf(ss), EPSQ);
    float v[8] = {a.x, a.y, a.z, a.w, b.x, b.y, b.z, b.w};
#pragma unroll
    for (int q = 0; q < 8; q++) {
        int k = lane * 8 + q;
        float x = v[q] * inv;
        g_cbs[(size_t)row * 256 + k] = x;
        g_Bh[(size_t)row * 256 + k] = __float2half_rn(x);
    }
}

// ---- main: M=128 CTA, chunk N=32 (32 chunks), warp grid 4x2, warp tile 32x16 ----
// smem: A_h 128x512B = 64KB @0; B 2 stages x 16KB @65536. 96KB -> 2 CTAs/SM.
__global__ void __launch_bounds__(256, 2)
quant_mma(const float* __restrict__ latent, const float* __restrict__ noise,
          const float* __restrict__ cb, const float* __restrict__ tptr,
          float* __restrict__ out, int K) {
    extern __shared__ char dsm[];
    __shared__ float s_scale[128];
    __shared__ float s_bv[256];
    __shared__ int s_bk2[256];
    __shared__ float s_sv[256];
    __shared__ int s_win[128];
    __shared__ int s_nfix;
    __shared__ int s_fixrows[16];
    __shared__ float s_rv[8];
    __shared__ int s_rk[8];

    const int tid = threadIdx.x, lane = tid & 31, wid = tid >> 5;
    const int wm = wid & 3, wn = wid >> 2;
    const int rowbase = blockIdx.x * 128;
    const uint32_t smA = smem_u32(dsm);
    const uint32_t smB = smA + 65536u;

    if (tid == 0) s_nfix = 0;

    // issue B chunks 0,1 (chunk = 32 rows x 512B, swizzled)
#pragma unroll
    for (int st = 0; st < 2; st++) {
#pragma unroll
        for (int i = 0; i < 4; i++) {
            int idx = tid + i * 256;
            int n = idx >> 5, c16 = idx & 31;
            uint32_t off = (uint32_t)(n * 512) + (uint32_t)((c16 * 16) ^ ((n & 7) << 4));
            cp16(smB + st * 16384u + off,
                 (const char*)g_Bh + ((size_t)(st * 32 + n) * 256 + c16 * 8) * 2);
        }
        cp_commit();
    }

    // A prologue: 2 threads per row, fp16 convert + swizzled store + row norm
    {
        float tv = *tptr;
        int r = tid >> 1, h2 = tid & 1;
        const float4* ar = (const float4*)(latent + (size_t)(rowbase + r) * 256);
        char* pA = dsm + r * 512;
        uint32_t swr = (uint32_t)((r & 7) << 4);
        float ss = 0.0f;
#pragma unroll
        for (int q = 0; q < 32; q++) {
            int d4 = h2 * 32 + q;
            float4 v = ar[d4];
            ss += v.x * v.x + v.y * v.y + v.z * v.z + v.w * v.w;
            __half h0 = __float2half_rn(v.x), h1 = __float2half_rn(v.y);
            __half h2a = __float2half_rn(v.z), h3 = __float2half_rn(v.w);
            uint2 hp;
            hp.x = (uint32_t)__half_as_ushort(h0) | ((uint32_t)__half_as_ushort(h1) << 16);
            hp.y = (uint32_t)__half_as_ushort(h2a) | ((uint32_t)__half_as_ushort(h3) << 16);
            *(uint2*)(pA + ((uint32_t)(d4 * 8) ^ swr)) = hp;
        }
        ss += __shfl_xor_sync(0xffffffffu, ss, 1);
        if (h2 == 0) s_scale[r] = 1.0f / (fmaxf(sqrtf(ss), EPSQ) * tv);
    }
    __syncthreads();

    // fragment address constants (verified in R4/R8)
    const int m8 = lane >> 3, rl = lane & 7;
    const uint32_t sw = (uint32_t)(rl << 4);
    const uint32_t aBase0 = smA + (uint32_t)((wm * 32 + 8 * (m8 & 1) + rl) * 512);
    const uint32_t aBase1 = aBase0 + 16 * 512;
    const uint32_t aKoff = (uint32_t)((m8 >> 1) * 16);
    const uint32_t bRow = (uint32_t)((wn * 16 + (m8 >> 1) * 8 + rl) * 512);
    const uint32_t bKoff = (uint32_t)((m8 & 1) * 16);

    // epilogue state: 4 owned rows
    const int eR = wm * 32 + (lane >> 2);
    const float* nrow[4];
    float sc[4], best[4], sec[4];
    int bk[4];
#pragma unroll
    for (int ri = 0; ri < 4; ri++) {
        int R = eR + (ri & 1) * 8 + (ri >> 1) * 16;
        nrow[ri] = noise + (size_t)(rowbase + R) * K;
        sc[ri] = s_scale[R];
        best[ri] = NEGINF; sec[ri] = NEGINF; bk[ri] = 0;
    }

    for (int c = 0; c < 32; c++) {
        // gumbel noise prefetch (overlaps cp wait)
        int cb0 = c * 32 + wn * 16 + (lane & 3) * 2;
        float2 u[4][2];
#pragma unroll
        for (int ri = 0; ri < 4; ri++) {
            u[ri][0] = *(const float2*)(nrow[ri] + cb0);
            u[ri][1] = *(const float2*)(nrow[ri] + cb0 + 8);
        }
        if (c < 31) cp_wait<1>(); else cp_wait<0>();
        __syncthreads();

        const uint32_t Bst = smB + (uint32_t)((c & 1) * 16384);
        float acc[2][2][4];
#pragma unroll
        for (int i = 0; i < 2; i++)
#pragma unroll
            for (int j = 0; j < 2; j++)
#pragma unroll
                for (int q = 0; q < 4; q++) acc[i][j][q] = 0.0f;

#pragma unroll
        for (int ks = 0; ks < 16; ks++) {
            uint32_t offA = ((uint32_t)(ks * 32) + aKoff) ^ sw;
            uint32_t offB = ((uint32_t)(ks * 32) + bKoff) ^ sw;
            uint32_t bh[4], a0[4], a1[4];
            ldsm4(bh, Bst + bRow + offB);
            ldsm4(a0, aBase0 + offA);
            ldsm4(a1, aBase1 + offA);
            mma16816(acc[0][0], a0, bh);
            mma16816(acc[0][1], a0, bh + 2);
            mma16816(acc[1][0], a1, bh);
            mma16816(acc[1][1], a1, bh + 2);
        }
        __syncthreads();

        // issue prefetch of c+2 immediately; epilogue overlaps the copy
        if (c + 2 < 32) {
            uint32_t stb = smB + (uint32_t)((c & 1) * 16384);
#pragma unroll
            for (int i = 0; i < 4; i++) {
                int idx = tid + i * 256;
                int n = idx >> 5, c16 = idx & 31;
                uint32_t off = (uint32_t)(n * 512) + (uint32_t)((c16 * 16) ^ ((n & 7) << 4));
                cp16(stb + off,
                     (const char*)g_Bh + ((size_t)((c + 2) * 32 + n) * 256 + c16 * 8) * 2);
            }
            cp_commit();
        }

        // epilogue: scale + fast gumbel (branchless) + running top-2
#pragma unroll
        for (int mt = 0; mt < 2; mt++)
#pragma unroll
            for (int hi = 0; hi < 2; hi++) {
                int ri = mt * 2 + hi;
                float b0 = best[ri], s0 = sec[ri];
                int k0 = bk[ri];
#pragma unroll
                for (int nt = 0; nt < 2; nt++) {
                    float2 uu = u[ri][nt];
                    float g0 = gumbel_fast(uu.x);
                    float g1 = gumbel_fast(uu.y);
                    float l0 = fmaf(acc[mt][nt][hi * 2 + 0], sc[ri], g0);
                    float l1 = fmaf(acc[mt][nt][hi * 2 + 1], sc[ri], g1);
                    int kk = cb0 + nt * 8;
                    if (l0 > b0) { s0 = b0; b0 = l0; k0 = kk; } else if (l0 > s0) s0 = l0;
                    if (l1 > b0) { s0 = b0; b0 = l1; k0 = kk + 1; } else if (l1 > s0) s0 = l1;
                }
                best[ri] = b0; sec[ri] = s0; bk[ri] = k0;
            }
    }

    // quad reduce: union top-2 (strict >, ties -> smaller k)
#pragma unroll
    for (int ri = 0; ri < 4; ri++) {
        float v = best[ri], s2 = sec[ri];
        int k = bk[ri];
#pragma unroll
        for (int off = 1; off <= 2; off <<= 1) {
            float ov = __shfl_xor_sync(0xffffffffu, v, off);
            float os = __shfl_xor_sync(0xffffffffu, s2, off);
            int ok = __shfl_xor_sync(0xffffffffu, k, off);
            float nb = fmaxf(v, ov);
            float ns = fmaxf(fminf(v, ov), fmaxf(s2, os));
            k = (ov > v || (ov == v && ok < k)) ? ok : k;
            v = nb; s2 = ns;
        }
        if ((lane & 3) == 0) {
            int R = eR + (ri & 1) * 8 + (ri >> 1) * 16;
            s_bv[R * 2 + wn] = v;
            s_sv[R * 2 + wn] = s2;
            s_bk2[R * 2 + wn] = k;
        }
    }
    __syncthreads();
    if (tid < 128) {
        float v0 = s_bv[tid * 2], v1 = s_bv[tid * 2 + 1];
        float q0 = s_sv[tid * 2], q1 = s_sv[tid * 2 + 1];
        int k0 = s_bk2[tid * 2], k1 = s_bk2[tid * 2 + 1];
        float vb = fmaxf(v0, v1);
        float vs = fmaxf(fminf(v0, v1), fmaxf(q0, q1));
        s_win[tid] = (v1 > v0 || (v1 == v0 && k1 < k0)) ? k1 : k0;
        if (vb - vs < TAU) {
            int i = atomicAdd(&s_nfix, 1);
            if (i < 16) s_fixrows[i] = tid;
        }
    }
    __syncthreads();

    // exact fp32 fixup for flagged rows (expected ~0.25 per CTA; accurate logf)
    int nf = s_nfix < 16 ? s_nfix : 16;
    for (int f = 0; f < nf; f++) {
        int r = s_fixrows[f];
        const float4* a4 = (const float4*)(latent + (size_t)(rowbase + r) * 256);
        const float* nz = noise + (size_t)(rowbase + r) * K;
        float scr = s_scale[r];
        float bv = NEGINF;
        int bki = 0;
        for (int k = tid; k < K; k += 256) {
            const float4* b4 = (const float4*)(g_cbs + (size_t)k * 256);
            float dot = 0.0f;
#pragma unroll 8
            for (int d4 = 0; d4 < 64; d4++) {
                float4 av = a4[d4], bb = b4[d4];
                dot = fmaf(av.x, bb.x, dot);
                dot = fmaf(av.y, bb.y, dot);
                dot = fmaf(av.z, bb.z, dot);
                dot = fmaf(av.w, bb.w, dot);
            }
            float lg = fmaf(dot, scr, -logf(-logf(nz[k])));
            if (lg > bv) { bv = lg; bki = k; }
        }
#pragma unroll
        for (int off = 16; off >= 1; off >>= 1) {
            float ov = __shfl_xor_sync(0xffffffffu, bv, off);
            int ok = __shfl_xor_sync(0xffffffffu, bki, off);
            if (ov > bv || (ov == bv && ok < bki)) { bv = ov; bki = ok; }
        }
        if (lane == 0) { s_rv[wid] = bv; s_rk[wid] = bki; }
        __syncthreads();
        if (tid == 0) {
            float v = s_rv[0]; int kk = s_rk[0];
#pragma unroll
            for (int w = 1; w < 8; w++)
                if (s_rv[w] > v || (s_rv[w] == v && s_rk[w] < kk)) { v = s_rv[w]; kk = s_rk[w]; }
            s_win[r] = kk;
        }
        __syncthreads();
    }

    // gather winning codebook rows (original fp32 codebook)
    const float4* cb4 = (const float4*)cb;
    float4* o4 = (float4*)out;
#pragma unroll
    for (int t = 0; t < 32; t++) {
        int idx = tid + t * 256;
        int r = idx >> 6, d4 = idx & 63;
        o4[(size_t)(rowbase + r) * 64 + d4] = cb4[(size_t)s_win[r] * 64 + d4];
    }
}

extern "C" void kernel_launch(void* const* d_in, const int* in_sizes, int n_in,
                              void* d_out, int out_size) {
    const float* latent = (const float*)d_in[0];
    const float* noise  = (const float*)d_in[1];
    const float* cb     = (const float*)d_in[2];
    const float* tptr   = (const float*)d_in[3];

    double s0 = (double)in_sizes[0], s1 = (double)in_sizes[1], s2 = (double)in_sizes[2];
    int D = (int)llround(sqrt(s0 * s2 / s1));   // 256
    int K = in_sizes[2] / D;                    // 1024
    int N = in_sizes[0] / D;                    // 131072

    prep_codebook<<<K / 8, 256>>>(cb, K);

    int shm = 98304;  // 96 KB dynamic -> 2 CTAs/SM
    cudaFuncSetAttribute(quant_mma, cudaFuncAttributeMaxDynamicSharedMemorySize, shm);
    quant_mma<<<N / 128, 256, shm>>>(latent, noise, cb, tptr, (float*)d_out, K);
}

// round 11
// speedup vs baseline: 1.4973x; 1.0200x over previous
#include <cuda_runtime.h>
#include <cuda_fp16.h>
#include <math.h>
#include <stdint.h>

#define EPSQ 1e-8f
#define TAU 2e-3f
#define NEGINF (-__int_as_float(0x7f800000))

// normalized codebook: fp32 (exact fixup) + fp16 (MMA), row-major [1024][256]
__device__ float g_cbs[1024 * 256];
__device__ __half g_Bh[1024 * 256];

__device__ __forceinline__ uint32_t smem_u32(const void* p) {
    uint32_t a;
    asm("{ .reg .u64 t; cvta.to.shared.u64 t, %1; cvt.u32.u64 %0, t; }" : "=r"(a) : "l"(p));
    return a;
}
__device__ __forceinline__ void cp16(uint32_t smem_dst, const void* gsrc) {
    asm volatile("cp.async.cg.shared.global [%0], [%1], 16;" :: "r"(smem_dst), "l"(gsrc));
}
__device__ __forceinline__ void cp_commit() { asm volatile("cp.async.commit_group;"); }
template <int Np>
__device__ __forceinline__ void cp_wait() { asm volatile("cp.async.wait_group %0;" :: "n"(Np)); }

__device__ __forceinline__ void ldsm4(uint32_t* r, uint32_t addr) {
    asm volatile("ldmatrix.sync.aligned.m8n8.x4.shared.b16 {%0,%1,%2,%3}, [%4];"
                 : "=r"(r[0]), "=r"(r[1]), "=r"(r[2]), "=r"(r[3]) : "r"(addr));
}
__device__ __forceinline__ void mma16816(float* d, const uint32_t* a, const uint32_t* b) {
    asm volatile(
        "mma.sync.aligned.m16n8k16.row.col.f32.f16.f16.f32 "
        "{%0,%1,%2,%3},{%4,%5,%6,%7},{%8,%9},{%0,%1,%2,%3};"
        : "+f"(d[0]), "+f"(d[1]), "+f"(d[2]), "+f"(d[3])
        : "r"(a[0]), "r"(a[1]), "r"(a[2]), "r"(a[3]), "r"(b[0]), "r"(b[1]));
}

// Branchless screening gumbel (validated R10). selp for u->1 hazard, no BSSY.
__device__ __forceinline__ float gumbel_fast(float u) {
    float d = u - 1.0f;
    float t_near = -d * fmaf(fmaf(0.33333334f, d, -0.5f), d, 1.0f);  // -log1p(d)
    float t_far;
    asm("lg2.approx.f32 %0, %1;" : "=f"(t_far) : "f"(u));
    t_far = t_far * (-0.6931472f);
    float t = (u > 0.999f) ? t_near : t_far;
    float g;
    asm("lg2.approx.f32 %0, %1;" : "=f"(g) : "f"(t));
    return g * (-0.6931472f);
}

// ---- prep: normalize rows -> g_cbs (fp32) + g_Bh (fp16) ----
__global__ void prep_codebook(const float* __restrict__ cb, int K) {
    int row = blockIdx.x * 8 + (threadIdx.x >> 5);
    int lane = threadIdx.x & 31;
    if (row >= K) return;
    const float4* src = (const float4*)(cb + (size_t)row * 256);
    float4 a = src[lane * 2], b = src[lane * 2 + 1];
    float ss = a.x*a.x + a.y*a.y + a.z*a.z + a.w*a.w + b.x*b.x + b.y*b.y + b.z*b.z + b.w*b.w;
#pragma unroll
    for (int off = 16; off; off >>= 1) ss += __shfl_xor_sync(0xffffffffu, ss, off);
    float inv = 1.0f / fmaxf(sqrtf(ss), EPSQ);
    float v[8] = {a.x, a.y, a.z, a.w, b.x, b.y, b.z, b.w};
#pragma unroll
    for (int q = 0; q < 8; q++) {
        int k = lane * 8 + q;
        float x = v[q] * inv;
        g_cbs[(size_t)row * 256 + k] = x;
        g_Bh[(size_t)row * 256 + k] = __float2half_rn(x);
    }
}

__device__ __forceinline__ void issue_B_chunk(uint32_t dst, int chunk, int tid) {
#pragma unroll
    for (int i = 0; i < 4; i++) {
        int idx = tid + i * 256;
        int n = idx >> 5, c16 = idx & 31;
        uint32_t off = (uint32_t)(n * 512) + (uint32_t)((c16 * 16) ^ ((n & 7) << 4));
        cp16(dst + off, (const char*)g_Bh + ((size_t)(chunk * 32 + n) * 256 + c16 * 8) * 2);
    }
    cp_commit();
}

// ---- main: M=128 CTA, chunk N=32 (32 chunks), warp grid 4x2, warp tile 32x16 ----
// smem: A_h 128x512B = 64KB @0; B 3 stages x 16KB @65536. 112KB -> 2 CTAs/SM.
// One __syncthreads per chunk: 3-stage ring makes the post-mainloop barrier unnecessary.
__global__ void __launch_bounds__(256, 2)
quant_mma(const float* __restrict__ latent, const float* __restrict__ noise,
          const float* __restrict__ cb, const float* __restrict__ tptr,
          float* __restrict__ out, int K) {
    extern __shared__ char dsm[];
    __shared__ float s_scale[128];
    __shared__ int s_nfix;
    __shared__ int s_fixrows[16];
    __shared__ float s_rv[8];
    __shared__ int s_rk[8];

    const int tid = threadIdx.x, lane = tid & 31, wid = tid >> 5;
    const int wm = wid & 3, wn = wid >> 2;
    const int rowbase = blockIdx.x * 128;
    const uint32_t smA = smem_u32(dsm);
    const uint32_t smB = smA + 65536u;

    if (tid == 0) s_nfix = 0;

    // prologue: issue B chunks 0,1 into stages 0,1
    issue_B_chunk(smB, 0, tid);
    issue_B_chunk(smB + 16384u, 1, tid);

    // A prologue: 2 threads per row, fp16 convert + swizzled store + row norm
    {
        float tv = *tptr;
        int r = tid >> 1, h2 = tid & 1;
        const float4* ar = (const float4*)(latent + (size_t)(rowbase + r) * 256);
        char* pA = dsm + r * 512;
        uint32_t swr = (uint32_t)((r & 7) << 4);
        float ss = 0.0f;
#pragma unroll
        for (int q = 0; q < 32; q++) {
            int d4 = h2 * 32 + q;
            float4 v = ar[d4];
            ss += v.x * v.x + v.y * v.y + v.z * v.z + v.w * v.w;
            __half h0 = __float2half_rn(v.x), h1 = __float2half_rn(v.y);
            __half h2a = __float2half_rn(v.z), h3 = __float2half_rn(v.w);
            uint2 hp;
            hp.x = (uint32_t)__half_as_ushort(h0) | ((uint32_t)__half_as_ushort(h1) << 16);
            hp.y = (uint32_t)__half_as_ushort(h2a) | ((uint32_t)__half_as_ushort(h3) << 16);
            *(uint2*)(pA + ((uint32_t)(d4 * 8) ^ swr)) = hp;
        }
        ss += __shfl_xor_sync(0xffffffffu, ss, 1);
        if (h2 == 0) s_scale[r] = 1.0f / (fmaxf(sqrtf(ss), EPSQ) * tv);
    }
    __syncthreads();

    // fragment address constants (verified R4/R8/R10)
    const int m8 = lane >> 3, rl = lane & 7;
    const uint32_t sw = (uint32_t)(rl << 4);
    const uint32_t aBase0 = smA + (uint32_t)((wm * 32 + 8 * (m8 & 1) + rl) * 512);
    const uint32_t aBase1 = aBase0 + 16 * 512;
    const uint32_t aKoff = (uint32_t)((m8 >> 1) * 16);
    const uint32_t bRow = (uint32_t)((wn * 16 + (m8 >> 1) * 8 + rl) * 512);
    const uint32_t bKoff = (uint32_t)((m8 & 1) * 16);

    // epilogue state: 4 owned rows
    const int eR = wm * 32 + (lane >> 2);
    const float* nrow[4];
    float sc[4], best[4], sec[4];
    int bk[4];
#pragma unroll
    for (int ri = 0; ri < 4; ri++) {
        int R = eR + (ri & 1) * 8 + (ri >> 1) * 16;
        nrow[ri] = noise + (size_t)(rowbase + R) * K;
        sc[ri] = s_scale[R];
        best[ri] = NEGINF; sec[ri] = NEGINF; bk[ri] = 0;
    }

    int rd = 0;  // ring read stage
    for (int c = 0; c < 32; c++) {
        // gumbel noise prefetch (overlaps cp wait)
        int cb0 = c * 32 + wn * 16 + (lane & 3) * 2;
        float2 u[4][2];
#pragma unroll
        for (int ri = 0; ri < 4; ri++) {
            u[ri][0] = *(const float2*)(nrow[ri] + cb0);
            u[ri][1] = *(const float2*)(nrow[ri] + cb0 + 8);
        }
        if (c < 31) cp_wait<1>(); else cp_wait<0>();
        __syncthreads();  // the ONLY barrier per chunk

        const uint32_t Bst = smB + (uint32_t)(rd * 16384);
        float acc[2][2][4];
#pragma unroll
        for (int i = 0; i < 2; i++)
#pragma unroll
            for (int j = 0; j < 2; j++)
#pragma unroll
                for (int q = 0; q < 4; q++) acc[i][j][q] = 0.0f;

#pragma unroll
        for (int ks = 0; ks < 16; ks++) {
            uint32_t offA = ((uint32_t)(ks * 32) + aKoff) ^ sw;
            uint32_t offB = ((uint32_t)(ks * 32) + bKoff) ^ sw;
            uint32_t bh[4], a0[4], a1[4];
            ldsm4(bh, Bst + bRow + offB);
            ldsm4(a0, aBase0 + offA);
            ldsm4(a1, aBase1 + offA);
            mma16816(acc[0][0], a0, bh);
            mma16816(acc[0][1], a0, bh + 2);
            mma16816(acc[1][0], a1, bh);
            mma16816(acc[1][1], a1, bh + 2);
        }

        // issue prefetch of c+2 into stage (rd+2)%3 = the stage chunk c-1 read;
        // safe without a barrier: every warp passed this chunk's top sync.
        if (c + 2 < 32) {
            int wst = (rd >= 1) ? rd - 1 : 2;
            issue_B_chunk(smB + (uint32_t)(wst * 16384), c + 2, tid);
        }

        // epilogue: scale + fast gumbel + running top-2
#pragma unroll
        for (int mt = 0; mt < 2; mt++)
#pragma unroll
            for (int hi = 0; hi < 2; hi++) {
                int ri = mt * 2 + hi;
                float b0 = best[ri], s0 = sec[ri];
                int k0 = bk[ri];
#pragma unroll
                for (int nt = 0; nt < 2; nt++) {
                    float2 uu = u[ri][nt];
                    float g0 = gumbel_fast(uu.x);
                    float g1 = gumbel_fast(uu.y);
                    float l0 = fmaf(acc[mt][nt][hi * 2 + 0], sc[ri], g0);
                    float l1 = fmaf(acc[mt][nt][hi * 2 + 1], sc[ri], g1);
                    int kk = cb0 + nt * 8;
                    if (l0 > b0) { s0 = b0; b0 = l0; k0 = kk; } else if (l0 > s0) s0 = l0;
                    if (l1 > b0) { s0 = b0; b0 = l1; k0 = kk + 1; } else if (l1 > s0) s0 = l1;
                }
                best[ri] = b0; sec[ri] = s0; bk[ri] = k0;
            }

        rd = (rd + 1 == 3) ? 0 : rd + 1;
    }

    // reduction scratch reuses the (now dead) A region of dynamic smem
    float* r_bv = (float*)dsm;            // [256]
    float* r_sv = (float*)(dsm + 1024);   // [256]
    int*   r_bk = (int*)(dsm + 2048);     // [256]
    int*   r_win = (int*)(dsm + 3072);    // [128]
    __syncthreads();  // all warps out of the mainloop before scribbling on A

    // quad reduce: union top-2 (strict >, ties -> smaller k)
#pragma unroll
    for (int ri = 0; ri < 4; ri++) {
        float v = best[ri], s2 = sec[ri];
        int k = bk[ri];
#pragma unroll
        for (int off = 1; off <= 2; off <<= 1) {
            float ov = __shfl_xor_sync(0xffffffffu, v, off);
            float os = __shfl_xor_sync(0xffffffffu, s2, off);
            int ok = __shfl_xor_sync(0xffffffffu, k, off);
            float nb = fmaxf(v, ov);
            float ns = fmaxf(fminf(v, ov), fmaxf(s2, os));
            k = (ov > v || (ov == v && ok < k)) ? ok : k;
            v = nb; s2 = ns;
        }
        if ((lane & 3) == 0) {
            int R = eR + (ri & 1) * 8 + (ri >> 1) * 16;
            r_bv[R * 2 + wn] = v;
            r_sv[R * 2 + wn] = s2;
            r_bk[R * 2 + wn] = k;
        }
    }
    __syncthreads();
    if (tid < 128) {
        float v0 = r_bv[tid * 2], v1 = r_bv[tid * 2 + 1];
        float q0 = r_sv[tid * 2], q1 = r_sv[tid * 2 + 1];
        int k0 = r_bk[tid * 2], k1 = r_bk[tid * 2 + 1];
        float vb = fmaxf(v0, v1);
        float vs = fmaxf(fminf(v0, v1), fmaxf(q0, q1));
        r_win[tid] = (v1 > v0 || (v1 == v0 && k1 < k0)) ? k1 : k0;
        if (vb - vs < TAU) {
            int i = atomicAdd(&s_nfix, 1);
            if (i < 16) s_fixrows[i] = tid;
        }
    }
    __syncthreads();

    // exact fp32 fixup for flagged rows (expected ~0.25 per CTA; accurate logf)
    int nf = s_nfix < 16 ? s_nfix : 16;
    for (int f = 0; f < nf; f++) {
        int r = s_fixrows[f];
        const float4* a4 = (const float4*)(latent + (size_t)(rowbase + r) * 256);
        const float* nz = noise + (size_t)(rowbase + r) * K;
        float scr = s_scale[r];
        float bv = NEGINF;
        int bki = 0;
        for (int k = tid; k < K; k += 256) {
            const float4* b4 = (const float4*)(g_cbs + (size_t)k * 256);
            float dot = 0.0f;
#pragma unroll 8
            for (int d4 = 0; d4 < 64; d4++) {
                float4 av = a4[d4], bb = b4[d4];
                dot = fmaf(av.x, bb.x, dot);
                dot = fmaf(av.y, bb.y, dot);
                dot = fmaf(av.z, bb.z, dot);
                dot = fmaf(av.w, bb.w, dot);
            }
            float lg = fmaf(dot, scr, -logf(-logf(nz[k])));
            if (lg > bv) { bv = lg; bki = k; }
        }
#pragma unroll
        for (int off = 16; off >= 1; off >>= 1) {
            float ov = __shfl_xor_sync(0xffffffffu, bv, off);
            int ok = __shfl_xor_sync(0xffffffffu, bki, off);
            if (ov > bv || (ov == bv && ok < bki)) { bv = ov; bki = ok; }
        }
        if (lane == 0) { s_rv[wid] = bv; s_rk[wid] = bki; }
        __syncthreads();
        if (tid == 0) {
            float v = s_rv[0]; int kk = s_rk[0];
#pragma unroll
            for (int w = 1; w < 8; w++)
                if (s_rv[w] > v || (s_rv[w] == v && s_rk[w] < kk)) { v = s_rv[w]; kk = s_rk[w]; }
            r_win[r] = kk;
        }
        __syncthreads();
    }

    // gather winning codebook rows (original fp32 codebook)
    const float4* cb4 = (const float4*)cb;
    float4* o4 = (float4*)out;
#pragma unroll
    for (int t = 0; t < 32; t++) {
        int idx = tid + t * 256;
        int r = idx >> 6, d4 = idx & 63;
        o4[(size_t)(rowbase + r) * 64 + d4] = cb4[(size_t)r_win[r] * 64 + d4];
    }
}

extern "C" void kernel_launch(void* const* d_in, const int* in_sizes, int n_in,
                              void* d_out, int out_size) {
    const float* latent = (const float*)d_in[0];
    const float* noise  = (const float*)d_in[1];
    const float* cb     = (const float*)d_in[2];
    const float* tptr   = (const float*)d_in[3];

    double s0 = (double)in_sizes[0], s1 = (double)in_sizes[1], s2 = (double)in_sizes[2];
    int D = (int)llround(sqrt(s0 * s2 / s1));   // 256
    int K = in_sizes[2] / D;                    // 1024
    int N = in_sizes[0] / D;                    // 131072

    prep_codebook<<<K / 8, 256>>>(cb, K);

    int shm = 114688;  // 112 KB dynamic (A 64K + B ring 48K) -> 2 CTAs/SM
    cudaFuncSetAttribute(quant_mma, cudaFuncAttributeMaxDynamicSharedMemorySize, shm);
    quant_mma<<<N / 128, 256, shm>>>(latent, noise, cb, tptr, (float*)d_out, K);
}